// round 2
// baseline (speedup 1.0000x reference)
#include <cuda_runtime.h>
#include <cstdint>

// Problem constants
#define BB   2048
#define HH   2048
#define RNK  64
#define LL   32

#define KT   64          // k sub-chunk staged in smem
#define NKG  8           // split-K output groups
#define KSUB 4           // sub-chunks per group (NKG*KSUB*KT == HH)
#define SC   64          // sample chunk
#define HT   64          // h tile for GEMM2
#define TPB  256

#define SZ_STRIDE 130    // floats per row of duplicated-z tile (2*SC + 2)
#define PJ_STRIDE 130    // floats per row of duplicated-proj tile
#define UT_STRIDE 68     // floats per row of transposed-u tile (HT + 4)

// Scratch (device globals — no allocations allowed)
__device__ int    g_offsets[LL + 1];
__device__ int    g_sorted[BB];
__device__ float  g_partial[(size_t)NKG * BB * RNK];   // 4 MB, indexed by sorted pos
__device__ float  g_proj[(size_t)BB * RNK];            // indexed by sorted pos

__device__ __forceinline__ uint32_t smem_u32(const void* p) {
    return (uint32_t)__cvta_generic_to_shared(p);
}
#define FFMA2(d, a, b, c) asm("fma.rn.f32x2 %0, %1, %2, %3;" : "=l"(d) : "l"(a), "l"(b), "l"(c))
#define ADDF2(d, a, b)    asm("add.rn.f32x2 %0, %1, %2;"     : "=l"(d) : "l"(a), "l"(b))
#define LDS2U64(a, b, addr) \
    asm volatile("ld.shared.v2.u64 {%0, %1}, [%2];" : "=l"(a), "=l"(b) : "r"(addr))
#define LDSU64(a, addr) \
    asm volatile("ld.shared.u64 %0, [%1];" : "=l"(a) : "r"(addr))

// ---------------------------------------------------------------------------
// Kernel 1: stable counting sort of samples by layer id (deterministic).
// ---------------------------------------------------------------------------
__global__ void setup_kernel(const int* __restrict__ ids) {
    __shared__ int A[LL * TPB];
    __shared__ int S[TPB];
    int t = threadIdx.x;

    #pragma unroll
    for (int l = 0; l < LL; l++) A[l * TPB + t] = 0;
    int seg = t * (BB / TPB);
    #pragma unroll
    for (int i = 0; i < BB / TPB; i++) {
        int lid = ids[seg + i];
        A[lid * TPB + t]++;
    }
    __syncthreads();

    int base = t * 32;
    int sum = 0;
    #pragma unroll
    for (int j = 0; j < 32; j++) { int x = A[base + j]; A[base + j] = sum; sum += x; }
    S[t] = sum;
    int mysum = sum;
    __syncthreads();
    for (int d = 1; d < TPB; d <<= 1) {
        int add = (t >= d) ? S[t - d] : 0;
        __syncthreads();
        S[t] += add;
        __syncthreads();
    }
    int excl = S[t] - mysum;
    #pragma unroll
    for (int j = 0; j < 32; j++) A[base + j] += excl;
    __syncthreads();

    if (t < LL) g_offsets[t] = A[t * TPB];
    if (t == 0) g_offsets[LL] = BB;

    #pragma unroll
    for (int i = 0; i < BB / TPB; i++) {
        int s = seg + i;
        int lid = ids[s];
        int p = A[lid * TPB + t];
        A[lid * TPB + t] = p + 1;
        g_sorted[p] = s;
    }
}

// ---------------------------------------------------------------------------
// Kernel 2: GEMM1 split-K with packed FFMA2.
// block = (k-group, layer). Each block accumulates over KSUB sub-chunks in regs.
// partial[kg][p][r] for p = sorted sample position.
// thread = 2 samples x 8 r.
// ---------------------------------------------------------------------------
__global__ __launch_bounds__(TPB) void proj_kernel(const float* __restrict__ z,
                                                   const float* __restrict__ v) {
    extern __shared__ __align__(16) float smem[];
    float* sv   = smem;                       // [KT][RNK]  16 KB
    float* szT2 = smem + KT * RNK;            // [KT][SZ_STRIDE] dup z  33.3 KB

    int t = threadIdx.x, lane = t & 31, w = t >> 5;
    int kg = blockIdx.x, l = blockIdx.y;
    int rc = (t & 7) * 8;
    int sc = (t >> 3) * 2;

    uint32_t sv_b = smem_u32(sv) + rc * 4;
    uint32_t sz_b = smem_u32(szT2) + sc * 8;

    int off = g_offsets[l];
    int cnt = g_offsets[l + 1] - off;

    for (int c0 = 0; c0 < cnt; c0 += SC) {
        int nc = min(SC, cnt - c0);
        unsigned long long a00 = 0, a01 = 0, a02 = 0, a03 = 0;
        unsigned long long a10 = 0, a11 = 0, a12 = 0, a13 = 0;

        for (int kk = 0; kk < KSUB; kk++) {
            int k0 = (kg * KSUB + kk) * KT;
            __syncthreads();
            // stage v tile (contiguous 16 KB)
            const float4* vs = (const float4*)(v + ((size_t)l * HH + k0) * RNK);
            float4* vd = (float4*)sv;
            #pragma unroll
            for (int i = 0; i < (KT * RNK / 4) / TPB; i++)
                vd[t + i * TPB] = vs[t + i * TPB];
            // stage z transposed + duplicated: szT2[k][2s],[2s+1] = z[gs][k0+k]
            for (int s = w; s < SC; s += 8) {
                if (s < nc) {
                    int gs = g_sorted[off + c0 + s];
                    const float* zr = z + (size_t)gs * HH + k0;
                    float z0 = zr[lane], z1 = zr[lane + 32];
                    *(float2*)&szT2[lane * SZ_STRIDE + 2 * s]        = make_float2(z0, z0);
                    *(float2*)&szT2[(lane + 32) * SZ_STRIDE + 2 * s] = make_float2(z1, z1);
                }
            }
            __syncthreads();

            if (sc < nc) {
                #pragma unroll 16
                for (int k = 0; k < KT; k++) {
                    unsigned long long v01, v23, v45, v67, z0, z1;
                    uint32_t va = sv_b + k * (RNK * 4);
                    LDS2U64(v01, v23, va);
                    LDS2U64(v45, v67, va + 16);
                    uint32_t za = sz_b + k * (SZ_STRIDE * 4);
                    LDSU64(z0, za);
                    LDSU64(z1, za + 8);
                    FFMA2(a00, v01, z0, a00); FFMA2(a01, v23, z0, a01);
                    FFMA2(a02, v45, z0, a02); FFMA2(a03, v67, z0, a03);
                    FFMA2(a10, v01, z1, a10); FFMA2(a11, v23, z1, a11);
                    FFMA2(a12, v45, z1, a12); FFMA2(a13, v67, z1, a13);
                }
            }
        }

        float* pb = g_partial + (size_t)kg * BB * RNK;
        int p0 = off + c0 + sc;
        if (sc < nc) {
            ulonglong2* d = (ulonglong2*)&pb[(size_t)p0 * RNK + rc];
            d[0] = make_ulonglong2(a00, a01);
            d[1] = make_ulonglong2(a02, a03);
        }
        if (sc + 1 < nc) {
            ulonglong2* d = (ulonglong2*)&pb[(size_t)(p0 + 1) * RNK + rc];
            d[0] = make_ulonglong2(a10, a11);
            d[1] = make_ulonglong2(a12, a13);
        }
    }
}

// ---------------------------------------------------------------------------
// Kernel 3: deterministic split-K reduction (8 groups).
// ---------------------------------------------------------------------------
__global__ void reduce_kernel() {
    int i = blockIdx.x * blockDim.x + threadIdx.x;
    const int n4 = BB * RNK / 4;
    if (i >= n4) return;
    const float4* p = (const float4*)g_partial;
    float4 s = p[i];
    #pragma unroll
    for (int kc = 1; kc < NKG; kc++) {
        float4 q = p[(size_t)kc * n4 + i];
        s.x += q.x; s.y += q.y; s.z += q.z; s.w += q.w;
    }
    ((float4*)g_proj)[i] = s;
}

// ---------------------------------------------------------------------------
// Kernel 4: GEMM2 + epilogue with packed FFMA2.
// block = (h-tile, layer). thread = 2 samples x 8 h.
// ---------------------------------------------------------------------------
__global__ __launch_bounds__(TPB) void out_kernel(const float* __restrict__ z,
                                                  const float* __restrict__ u,
                                                  float* __restrict__ out) {
    extern __shared__ __align__(16) float smem[];
    float* ut   = smem;                       // [RNK][UT_STRIDE] u transposed 17.4 KB
    float* pjT2 = smem + RNK * UT_STRIDE;     // [RNK][PJ_STRIDE] dup proj 33.3 KB
    int*   sgs  = (int*)(smem + RNK * UT_STRIDE + RNK * PJ_STRIDE);

    int t = threadIdx.x, lane = t & 31, w = t >> 5;
    int ht = blockIdx.x, l = blockIdx.y;
    int h0 = ht * HT;
    int hc = (t & 7) * 8;
    int sc = (t >> 3) * 2;

    uint32_t ut_b = smem_u32(ut) + hc * 4;
    uint32_t pj_b = smem_u32(pjT2) + sc * 8;

    // stage u transposed: ut[r][h] = u[l][h0+h][r]
    for (int h = w; h < HT; h += 8) {
        const float* ur = u + ((size_t)l * HH + h0 + h) * RNK;
        ut[lane * UT_STRIDE + h]        = ur[lane];
        ut[(lane + 32) * UT_STRIDE + h] = ur[lane + 32];
    }

    int off = g_offsets[l];
    int cnt = g_offsets[l + 1] - off;

    for (int c0 = 0; c0 < cnt; c0 += SC) {
        int nc = min(SC, cnt - c0);
        __syncthreads();    // ut ready / previous chunk consumed
        for (int s = w; s < SC; s += 8) {
            if (s < nc) {
                int gs = g_sorted[off + c0 + s];
                if (lane == 0) sgs[s] = gs;
                const float* pr = g_proj + (size_t)(off + c0 + s) * RNK;
                float p0 = pr[lane], p1 = pr[lane + 32];
                *(float2*)&pjT2[lane * PJ_STRIDE + 2 * s]        = make_float2(p0, p0);
                *(float2*)&pjT2[(lane + 32) * PJ_STRIDE + 2 * s] = make_float2(p1, p1);
            }
        }
        __syncthreads();

        if (sc < nc) {
            unsigned long long a00 = 0, a01 = 0, a02 = 0, a03 = 0;
            unsigned long long a10 = 0, a11 = 0, a12 = 0, a13 = 0;
            #pragma unroll 16
            for (int r = 0; r < RNK; r++) {
                unsigned long long u01, u23, u45, u67, p0, p1;
                uint32_t ua = ut_b + r * (UT_STRIDE * 4);
                LDS2U64(u01, u23, ua);
                LDS2U64(u45, u67, ua + 16);
                uint32_t pa = pj_b + r * (PJ_STRIDE * 4);
                LDSU64(p0, pa);
                LDSU64(p1, pa + 8);
                FFMA2(a00, u01, p0, a00); FFMA2(a01, u23, p0, a01);
                FFMA2(a02, u45, p0, a02); FFMA2(a03, u67, p0, a03);
                FFMA2(a10, u01, p1, a10); FFMA2(a11, u23, p1, a11);
                FFMA2(a12, u45, p1, a12); FFMA2(a13, u67, p1, a13);
            }
            // epilogue: out = z + delta
            {
                int gs = sgs[sc];
                const ulonglong2* zz = (const ulonglong2*)&z[(size_t)gs * HH + h0 + hc];
                ulonglong2 q0 = zz[0], q1 = zz[1];
                ADDF2(a00, a00, q0.x); ADDF2(a01, a01, q0.y);
                ADDF2(a02, a02, q1.x); ADDF2(a03, a03, q1.y);
                ulonglong2* o = (ulonglong2*)&out[(size_t)gs * HH + h0 + hc];
                o[0] = make_ulonglong2(a00, a01);
                o[1] = make_ulonglong2(a02, a03);
            }
            if (sc + 1 < nc) {
                int gs = sgs[sc + 1];
                const ulonglong2* zz = (const ulonglong2*)&z[(size_t)gs * HH + h0 + hc];
                ulonglong2 q0 = zz[0], q1 = zz[1];
                ADDF2(a10, a10, q0.x); ADDF2(a11, a11, q0.y);
                ADDF2(a12, a12, q1.x); ADDF2(a13, a13, q1.y);
                ulonglong2* o = (ulonglong2*)&out[(size_t)gs * HH + h0 + hc];
                o[0] = make_ulonglong2(a10, a11);
                o[1] = make_ulonglong2(a12, a13);
            }
        }
    }
}

// ---------------------------------------------------------------------------
extern "C" void kernel_launch(void* const* d_in, const int* in_sizes, int n_in,
                              void* d_out, int out_size) {
    const float* z   = (const float*)d_in[0];
    const int*   ids = (const int*)  d_in[1];
    const float* u   = (const float*)d_in[2];
    const float* v   = (const float*)d_in[3];
    float*       out = (float*)d_out;

    const int proj_smem = (KT * RNK + KT * SZ_STRIDE) * 4;
    const int out_smem  = (RNK * UT_STRIDE + RNK * PJ_STRIDE) * 4 + SC * 4;
    cudaFuncSetAttribute(proj_kernel, cudaFuncAttributeMaxDynamicSharedMemorySize, proj_smem);
    cudaFuncSetAttribute(out_kernel,  cudaFuncAttributeMaxDynamicSharedMemorySize, out_smem);

    setup_kernel<<<1, TPB>>>(ids);
    proj_kernel<<<dim3(NKG, LL), TPB, proj_smem>>>(z, v);
    reduce_kernel<<<(BB * RNK / 4 + TPB - 1) / TPB, TPB>>>();
    out_kernel<<<dim3(HH / HT, LL), TPB, out_smem>>>(z, u, out);
}

// round 3
// speedup vs baseline: 1.6711x; 1.6711x over previous
#include <cuda_runtime.h>
#include <cstdint>

// Problem constants
#define BB   2048
#define HH   2048
#define RNK  64
#define LL   32

#define KT   64          // k sub-chunk staged in smem
#define NKG  16          // split-K output groups
#define KSUB 2           // sub-chunks per group (NKG*KSUB*KT == HH)
#define SC   64          // sample chunk
#define HT   64          // h tile for GEMM2
#define TPB  256

#define SZ_STRIDE 132    // floats per row of duplicated-z tile (16B-aligned rows)
#define PJ_STRIDE 132    // floats per row of duplicated-proj tile
#define UT_STRIDE 68     // floats per row of transposed-u tile (272B = 16*17)

// Scratch (device globals — no allocations allowed)
__device__ int    g_offsets[LL + 1];
__device__ int    g_sorted[BB];
__device__ float  g_partial[(size_t)NKG * BB * RNK];   // 8 MB, indexed by sorted pos
__device__ float  g_proj[(size_t)BB * RNK];            // indexed by sorted pos

// Pure (non-volatile) packed-math asm: register-only, ptxas may schedule freely.
#define FFMA2(d, a, b, c) asm("fma.rn.f32x2 %0, %1, %2, %3;" : "=l"(d) : "l"(a), "l"(b), "l"(c))
#define ADDF2(d, a, b)    asm("add.rn.f32x2 %0, %1, %2;"     : "=l"(d) : "l"(a), "l"(b))

typedef unsigned long long u64;

// ---------------------------------------------------------------------------
// Kernel 1: stable counting sort of samples by layer id (deterministic).
// ---------------------------------------------------------------------------
__global__ void setup_kernel(const int* __restrict__ ids) {
    __shared__ int A[LL * TPB];
    __shared__ int S[TPB];
    int t = threadIdx.x;

    #pragma unroll
    for (int l = 0; l < LL; l++) A[l * TPB + t] = 0;
    int seg = t * (BB / TPB);
    #pragma unroll
    for (int i = 0; i < BB / TPB; i++) {
        int lid = ids[seg + i];
        A[lid * TPB + t]++;
    }
    __syncthreads();

    int base = t * 32;
    int sum = 0;
    #pragma unroll
    for (int j = 0; j < 32; j++) { int x = A[base + j]; A[base + j] = sum; sum += x; }
    S[t] = sum;
    int mysum = sum;
    __syncthreads();
    for (int d = 1; d < TPB; d <<= 1) {
        int add = (t >= d) ? S[t - d] : 0;
        __syncthreads();
        S[t] += add;
        __syncthreads();
    }
    int excl = S[t] - mysum;
    #pragma unroll
    for (int j = 0; j < 32; j++) A[base + j] += excl;
    __syncthreads();

    if (t < LL) g_offsets[t] = A[t * TPB];
    if (t == 0) g_offsets[LL] = BB;

    #pragma unroll
    for (int i = 0; i < BB / TPB; i++) {
        int s = seg + i;
        int lid = ids[s];
        int p = A[lid * TPB + t];
        A[lid * TPB + t] = p + 1;
        g_sorted[p] = s;
    }
}

// ---------------------------------------------------------------------------
// Kernel 2: GEMM1 split-K with packed FFMA2, C++ smem loads (schedulable).
// block = (k-group, layer). thread = 2 samples x 8 r.
// partial[kg][p][r] for p = sorted sample position.
// ---------------------------------------------------------------------------
__global__ __launch_bounds__(TPB) void proj_kernel(const float* __restrict__ z,
                                                   const float* __restrict__ v) {
    extern __shared__ __align__(16) float smem[];
    float* sv   = smem;                       // [KT][RNK]        16 KB
    float* szT2 = smem + KT * RNK;            // [KT][SZ_STRIDE]  33.8 KB (dup z)

    int t = threadIdx.x, lane = t & 31, w = t >> 5;
    int kg = blockIdx.x, l = blockIdx.y;
    int rc  = (t & 7) * 8;       // 8 r per thread
    int sc2 = (t >> 3) * 2;      // 2 samples per thread (even)

    int off = g_offsets[l];
    int cnt = g_offsets[l + 1] - off;

    for (int c0 = 0; c0 < cnt; c0 += SC) {
        int nc = min(SC, cnt - c0);
        u64 a00 = 0, a01 = 0, a02 = 0, a03 = 0;
        u64 a10 = 0, a11 = 0, a12 = 0, a13 = 0;

        #pragma unroll
        for (int kk = 0; kk < KSUB; kk++) {
            int k0 = (kg * KSUB + kk) * KT;
            __syncthreads();
            // stage v tile (contiguous 16 KB)
            const float4* vs = (const float4*)(v + ((size_t)l * HH + k0) * RNK);
            float4* vd = (float4*)sv;
            #pragma unroll
            for (int i = 0; i < (KT * RNK / 4) / TPB; i++)
                vd[t + i * TPB] = vs[t + i * TPB];
            // stage z transposed + duplicated: szT2[k][2s],[2s+1] = z[gs][k0+k]
            for (int s = w; s < SC; s += 8) {
                if (s < nc) {
                    int gs = g_sorted[off + c0 + s];
                    const float* zr = z + (size_t)gs * HH + k0;
                    float z0 = zr[lane], z1 = zr[lane + 32];
                    *(float2*)&szT2[lane * SZ_STRIDE + 2 * s]        = make_float2(z0, z0);
                    *(float2*)&szT2[(lane + 32) * SZ_STRIDE + 2 * s] = make_float2(z1, z1);
                }
            }
            __syncthreads();

            if (sc2 < nc) {
                #pragma unroll 8
                for (int k = 0; k < KT; k++) {
                    const ulonglong2* vp = (const ulonglong2*)(sv + k * RNK + rc);
                    ulonglong2 vA = vp[0], vB = vp[1];
                    ulonglong2 zz = *(const ulonglong2*)(szT2 + k * SZ_STRIDE + 2 * sc2);
                    FFMA2(a00, vA.x, zz.x, a00); FFMA2(a01, vA.y, zz.x, a01);
                    FFMA2(a02, vB.x, zz.x, a02); FFMA2(a03, vB.y, zz.x, a03);
                    FFMA2(a10, vA.x, zz.y, a10); FFMA2(a11, vA.y, zz.y, a11);
                    FFMA2(a12, vB.x, zz.y, a12); FFMA2(a13, vB.y, zz.y, a13);
                }
            }
        }

        float* pb = g_partial + (size_t)kg * BB * RNK;
        int p0 = off + c0 + sc2;
        if (sc2 < nc) {
            ulonglong2* d = (ulonglong2*)&pb[(size_t)p0 * RNK + rc];
            d[0] = make_ulonglong2(a00, a01);
            d[1] = make_ulonglong2(a02, a03);
        }
        if (sc2 + 1 < nc) {
            ulonglong2* d = (ulonglong2*)&pb[(size_t)(p0 + 1) * RNK + rc];
            d[0] = make_ulonglong2(a10, a11);
            d[1] = make_ulonglong2(a12, a13);
        }
    }
}

// ---------------------------------------------------------------------------
// Kernel 3: deterministic split-K reduction (16 groups).
// ---------------------------------------------------------------------------
__global__ void reduce_kernel() {
    int i = blockIdx.x * blockDim.x + threadIdx.x;
    const int n4 = BB * RNK / 4;
    if (i >= n4) return;
    const float4* p = (const float4*)g_partial;
    float4 s = p[i];
    #pragma unroll
    for (int kc = 1; kc < NKG; kc++) {
        float4 q = p[(size_t)kc * n4 + i];
        s.x += q.x; s.y += q.y; s.z += q.z; s.w += q.w;
    }
    ((float4*)g_proj)[i] = s;
}

// ---------------------------------------------------------------------------
// Kernel 4: GEMM2 + epilogue with packed FFMA2, C++ smem loads.
// block = (h-tile, layer). thread = 2 samples x 8 h.
// ---------------------------------------------------------------------------
__global__ __launch_bounds__(TPB) void out_kernel(const float* __restrict__ z,
                                                  const float* __restrict__ u,
                                                  float* __restrict__ out) {
    extern __shared__ __align__(16) float smem[];
    float* ut   = smem;                       // [RNK][UT_STRIDE]  17.4 KB (u transposed)
    float* pjT2 = smem + RNK * UT_STRIDE;     // [RNK][PJ_STRIDE]  33.8 KB (dup proj)
    int*   sgs  = (int*)(smem + RNK * UT_STRIDE + RNK * PJ_STRIDE);

    int t = threadIdx.x, lane = t & 31, w = t >> 5;
    int ht = blockIdx.x, l = blockIdx.y;
    int h0 = ht * HT;
    int hc  = (t & 7) * 8;       // 8 h per thread
    int sc2 = (t >> 3) * 2;      // 2 samples per thread

    // stage u transposed: ut[r][h] = u[l][h0+h][r]
    for (int h = w; h < HT; h += 8) {
        const float* ur = u + ((size_t)l * HH + h0 + h) * RNK;
        ut[lane * UT_STRIDE + h]        = ur[lane];
        ut[(lane + 32) * UT_STRIDE + h] = ur[lane + 32];
    }

    int off = g_offsets[l];
    int cnt = g_offsets[l + 1] - off;

    for (int c0 = 0; c0 < cnt; c0 += SC) {
        int nc = min(SC, cnt - c0);
        __syncthreads();   // ut ready / previous chunk consumed
        for (int s = w; s < SC; s += 8) {
            if (s < nc) {
                int gs = g_sorted[off + c0 + s];
                if (lane == 0) sgs[s] = gs;
                const float* pr = g_proj + (size_t)(off + c0 + s) * RNK;
                float p0 = pr[lane], p1 = pr[lane + 32];
                *(float2*)&pjT2[lane * PJ_STRIDE + 2 * s]        = make_float2(p0, p0);
                *(float2*)&pjT2[(lane + 32) * PJ_STRIDE + 2 * s] = make_float2(p1, p1);
            }
        }
        __syncthreads();

        if (sc2 < nc) {
            u64 a00 = 0, a01 = 0, a02 = 0, a03 = 0;
            u64 a10 = 0, a11 = 0, a12 = 0, a13 = 0;
            #pragma unroll 8
            for (int r = 0; r < RNK; r++) {
                const ulonglong2* up = (const ulonglong2*)(ut + r * UT_STRIDE + hc);
                ulonglong2 uA = up[0], uB = up[1];
                ulonglong2 pp = *(const ulonglong2*)(pjT2 + r * PJ_STRIDE + 2 * sc2);
                FFMA2(a00, uA.x, pp.x, a00); FFMA2(a01, uA.y, pp.x, a01);
                FFMA2(a02, uB.x, pp.x, a02); FFMA2(a03, uB.y, pp.x, a03);
                FFMA2(a10, uA.x, pp.y, a10); FFMA2(a11, uA.y, pp.y, a11);
                FFMA2(a12, uB.x, pp.y, a12); FFMA2(a13, uB.y, pp.y, a13);
            }
            // epilogue: out = z + delta
            {
                int gs = sgs[sc2];
                const ulonglong2* zz = (const ulonglong2*)&z[(size_t)gs * HH + h0 + hc];
                ulonglong2 q0 = zz[0], q1 = zz[1];
                ADDF2(a00, a00, q0.x); ADDF2(a01, a01, q0.y);
                ADDF2(a02, a02, q1.x); ADDF2(a03, a03, q1.y);
                ulonglong2* o = (ulonglong2*)&out[(size_t)gs * HH + h0 + hc];
                o[0] = make_ulonglong2(a00, a01);
                o[1] = make_ulonglong2(a02, a03);
            }
            if (sc2 + 1 < nc) {
                int gs = sgs[sc2 + 1];
                const ulonglong2* zz = (const ulonglong2*)&z[(size_t)gs * HH + h0 + hc];
                ulonglong2 q0 = zz[0], q1 = zz[1];
                ADDF2(a10, a10, q0.x); ADDF2(a11, a11, q0.y);
                ADDF2(a12, a12, q1.x); ADDF2(a13, a13, q1.y);
                ulonglong2* o = (ulonglong2*)&out[(size_t)gs * HH + h0 + hc];
                o[0] = make_ulonglong2(a10, a11);
                o[1] = make_ulonglong2(a12, a13);
            }
        }
    }
}

// ---------------------------------------------------------------------------
extern "C" void kernel_launch(void* const* d_in, const int* in_sizes, int n_in,
                              void* d_out, int out_size) {
    const float* z   = (const float*)d_in[0];
    const int*   ids = (const int*)  d_in[1];
    const float* u   = (const float*)d_in[2];
    const float* v   = (const float*)d_in[3];
    float*       out = (float*)d_out;

    const int proj_smem = (KT * RNK + KT * SZ_STRIDE) * 4;
    const int out_smem  = (RNK * UT_STRIDE + RNK * PJ_STRIDE) * 4 + SC * 4;
    cudaFuncSetAttribute(proj_kernel, cudaFuncAttributeMaxDynamicSharedMemorySize, proj_smem);
    cudaFuncSetAttribute(out_kernel,  cudaFuncAttributeMaxDynamicSharedMemorySize, out_smem);

    setup_kernel<<<1, TPB>>>(ids);
    proj_kernel<<<dim3(NKG, LL), TPB, proj_smem>>>(z, v);
    reduce_kernel<<<(BB * RNK / 4 + TPB - 1) / TPB, TPB>>>();
    out_kernel<<<dim3(HH / HT, LL), TPB, out_smem>>>(z, u, out);
}

// round 4
// speedup vs baseline: 3.5503x; 2.1245x over previous
#include <cuda_runtime.h>
#include <cstdint>

// Problem constants
#define BB   2048
#define HH   2048
#define RNK  64
#define LL   32

#define NKG  16          // split-K groups for GEMM1 (k per block = 128)
#define KCH  (HH / NKG)  // 128
#define MT   64          // M tile (samples)
#define HT   128         // h tile for GEMM2
#define TPB  128         // 4 warps
#define ST   72          // padded smem row stride (72 mod 32 == 8 -> conflict-free frags)

// Scratch (device globals — no allocations allowed)
__device__ int    g_offsets[LL + 1];
__device__ int    g_sorted[BB];
__device__ float  g_partial[(size_t)NKG * BB * RNK];   // 8 MB, indexed by sorted pos
__device__ float  g_proj[(size_t)BB * RNK];            // indexed by sorted pos

__device__ __forceinline__ uint32_t f2tf(float f) {
    uint32_t o;
    asm("cvt.rna.tf32.f32 %0, %1;" : "=r"(o) : "f"(f));
    return o;
}

#define MMA_TF32(c0,c1,c2,c3,a0,a1,a2,a3,b0,b1)                         \
    asm("mma.sync.aligned.m16n8k8.row.col.f32.tf32.tf32.f32 "           \
        "{%0,%1,%2,%3}, {%4,%5,%6,%7}, {%8,%9}, {%0,%1,%2,%3};"         \
        : "+f"(c0), "+f"(c1), "+f"(c2), "+f"(c3)                        \
        : "r"(a0), "r"(a1), "r"(a2), "r"(a3), "r"(b0), "r"(b1))

// ---------------------------------------------------------------------------
// Kernel 1: stable counting sort of samples by layer id (deterministic).
// ---------------------------------------------------------------------------
__global__ void setup_kernel(const int* __restrict__ ids) {
    __shared__ int A[LL * 256];
    __shared__ int S[256];
    int t = threadIdx.x;

    #pragma unroll
    for (int l = 0; l < LL; l++) A[l * 256 + t] = 0;
    int seg = t * (BB / 256);
    #pragma unroll
    for (int i = 0; i < BB / 256; i++) {
        int lid = ids[seg + i];
        A[lid * 256 + t]++;
    }
    __syncthreads();

    int base = t * 32;
    int sum = 0;
    #pragma unroll
    for (int j = 0; j < 32; j++) { int x = A[base + j]; A[base + j] = sum; sum += x; }
    S[t] = sum;
    int mysum = sum;
    __syncthreads();
    for (int d = 1; d < 256; d <<= 1) {
        int add = (t >= d) ? S[t - d] : 0;
        __syncthreads();
        S[t] += add;
        __syncthreads();
    }
    int excl = S[t] - mysum;
    #pragma unroll
    for (int j = 0; j < 32; j++) A[base + j] += excl;
    __syncthreads();

    if (t < LL) g_offsets[t] = A[t * 256];
    if (t == 0) g_offsets[LL] = BB;

    #pragma unroll
    for (int i = 0; i < BB / 256; i++) {
        int s = seg + i;
        int lid = ids[s];
        int p = A[lid * 256 + t];
        A[lid * 256 + t] = p + 1;
        g_sorted[p] = s;
    }
}

// ---------------------------------------------------------------------------
// Kernel 2: GEMM1 split-K with tf32 mma.
// block = (kg, layer); 4 warps; warp w handles m16 tile w of an MT=64 M-tile.
// partial[kg][p][r] = sum_{k in chunk} v[l][k][r] * z[sorted[p]][k]
// ---------------------------------------------------------------------------
__global__ __launch_bounds__(TPB) void proj_kernel(const float* __restrict__ z,
                                                   const float* __restrict__ v) {
    extern __shared__ __align__(16) uint32_t smem1[];
    uint32_t* sz = smem1;              // [MT][ST]  z tile (tf32 bits)   18 KB
    uint32_t* sv = smem1 + MT * ST;    // [KCHsub=64][ST] v tile (tf32)  18 KB

    int t = threadIdx.x, lane = t & 31, w = t >> 5;
    int gid = lane >> 2, tig = lane & 3;
    int kg = blockIdx.x, l = blockIdx.y;

    int off = g_offsets[l];
    int cnt = g_offsets[l + 1] - off;

    for (int m0 = 0; m0 < cnt; m0 += MT) {
        int nc = min(MT, cnt - m0);

        float acc[8][4];
        #pragma unroll
        for (int j = 0; j < 8; j++)
            #pragma unroll
            for (int q = 0; q < 4; q++) acc[j][q] = 0.0f;

        #pragma unroll
        for (int kk = 0; kk < KCH / 64; kk++) {
            int k0 = kg * KCH + kk * 64;
            __syncthreads();
            // stage z tile: rows = samples (pad w/ zeros), cols = 64 k, tf32
            #pragma unroll
            for (int i = 0; i < (MT * 64 / 4) / TPB; i++) {
                int idx = t + i * TPB;              // over 1024 float4s
                int row = idx >> 4, c4 = idx & 15;
                uint4 d = make_uint4(0u, 0u, 0u, 0u);
                if (row < nc) {
                    int gs = g_sorted[off + m0 + row];
                    float4 f = *(const float4*)&z[(size_t)gs * HH + k0 + c4 * 4];
                    d = make_uint4(f2tf(f.x), f2tf(f.y), f2tf(f.z), f2tf(f.w));
                }
                *(uint4*)&sz[row * ST + c4 * 4] = d;
            }
            // stage v tile: rows = k (64), cols = r (64), tf32
            #pragma unroll
            for (int i = 0; i < (64 * 64 / 4) / TPB; i++) {
                int idx = t + i * TPB;
                int row = idx >> 4, c4 = idx & 15;
                float4 f = *(const float4*)&v[((size_t)l * HH + k0 + row) * RNK + c4 * 4];
                *(uint4*)&sv[row * ST + c4 * 4] =
                    make_uint4(f2tf(f.x), f2tf(f.y), f2tf(f.z), f2tf(f.w));
            }
            __syncthreads();

            const uint32_t* szr = sz + (w * 16 + gid) * ST;
            #pragma unroll
            for (int ks = 0; ks < 8; ks++) {
                int kb = ks * 8 + tig;
                uint32_t a0 = szr[kb];
                uint32_t a1 = szr[8 * ST + kb];
                uint32_t a2 = szr[kb + 4];
                uint32_t a3 = szr[8 * ST + kb + 4];
                #pragma unroll
                for (int j = 0; j < 8; j++) {
                    uint32_t b0 = sv[kb * ST + j * 8 + gid];
                    uint32_t b1 = sv[(kb + 4) * ST + j * 8 + gid];
                    MMA_TF32(acc[j][0], acc[j][1], acc[j][2], acc[j][3],
                             a0, a1, a2, a3, b0, b1);
                }
            }
        }

        // store partials: c0/c1 -> (row=gid, col=2*tig), c2/c3 -> row+8
        float* pb = g_partial + (size_t)kg * BB * RNK;
        int rbase = w * 16 + gid;
        #pragma unroll
        for (int j = 0; j < 8; j++) {
            int col = j * 8 + 2 * tig;
            if (rbase < nc)
                *(float2*)&pb[(size_t)(off + m0 + rbase) * RNK + col] =
                    make_float2(acc[j][0], acc[j][1]);
            if (rbase + 8 < nc)
                *(float2*)&pb[(size_t)(off + m0 + rbase + 8) * RNK + col] =
                    make_float2(acc[j][2], acc[j][3]);
        }
    }
}

// ---------------------------------------------------------------------------
// Kernel 3: deterministic split-K reduction (16 groups).
// ---------------------------------------------------------------------------
__global__ void reduce_kernel() {
    int i = blockIdx.x * blockDim.x + threadIdx.x;
    const int n4 = BB * RNK / 4;
    if (i >= n4) return;
    const float4* p = (const float4*)g_partial;
    float4 s = p[i];
    #pragma unroll
    for (int kc = 1; kc < NKG; kc++) {
        float4 q = p[(size_t)kc * n4 + i];
        s.x += q.x; s.y += q.y; s.z += q.z; s.w += q.w;
    }
    ((float4*)g_proj)[i] = s;
}

// ---------------------------------------------------------------------------
// Kernel 4: GEMM2 + epilogue with tf32 mma.
// block = (h-tile 128, layer); warp w handles n range [w*32, w*32+32), all M.
// out[gs][h] = z[gs][h] + sum_r u[l][h][r] * proj[p][r]
// ---------------------------------------------------------------------------
__global__ __launch_bounds__(TPB) void out_kernel(const float* __restrict__ z,
                                                  const float* __restrict__ u,
                                                  float* __restrict__ out) {
    extern __shared__ __align__(16) uint32_t smem2[];
    uint32_t* sp = smem2;              // [MT][ST]  proj tile (tf32)  18 KB
    uint32_t* su = smem2 + MT * ST;    // [HT][ST]  u tile (tf32)     36 KB

    int t = threadIdx.x, lane = t & 31, w = t >> 5;
    int gid = lane >> 2, tig = lane & 3;
    int hb = blockIdx.x, l = blockIdx.y;
    int h0 = hb * HT;

    int off = g_offsets[l];
    int cnt = g_offsets[l + 1] - off;
    if (cnt == 0) return;

    // stage u tile once: su[h][r] = tf32(u[l][h0+h][r]), rows h (128), cols r (64)
    #pragma unroll
    for (int i = 0; i < (HT * RNK / 4) / TPB; i++) {
        int idx = t + i * TPB;
        int row = idx >> 4, c4 = idx & 15;
        float4 f = *(const float4*)&u[((size_t)l * HH + h0 + row) * RNK + c4 * 4];
        *(uint4*)&su[row * ST + c4 * 4] =
            make_uint4(f2tf(f.x), f2tf(f.y), f2tf(f.z), f2tf(f.w));
    }

    for (int m0 = 0; m0 < cnt; m0 += MT) {
        int nc = min(MT, cnt - m0);
        __syncthreads();   // su ready / previous sp consumed
        // stage proj tile: rows = samples (pad), cols = r
        #pragma unroll
        for (int i = 0; i < (MT * RNK / 4) / TPB; i++) {
            int idx = t + i * TPB;
            int row = idx >> 4, c4 = idx & 15;
            uint4 d = make_uint4(0u, 0u, 0u, 0u);
            if (row < nc) {
                float4 f = *(const float4*)&g_proj[(size_t)(off + m0 + row) * RNK + c4 * 4];
                d = make_uint4(f2tf(f.x), f2tf(f.y), f2tf(f.z), f2tf(f.w));
            }
            *(uint4*)&sp[row * ST + c4 * 4] = d;
        }
        __syncthreads();

        float acc[4][4][4];   // [mtile][nsub][reg]
        #pragma unroll
        for (int mt = 0; mt < 4; mt++)
            #pragma unroll
            for (int j = 0; j < 4; j++)
                #pragma unroll
                for (int q = 0; q < 4; q++) acc[mt][j][q] = 0.0f;

        #pragma unroll
        for (int ks = 0; ks < 8; ks++) {
            int kb = ks * 8 + tig;
            uint32_t b0[4], b1[4];
            #pragma unroll
            for (int j = 0; j < 4; j++) {
                int n = w * 32 + j * 8 + gid;
                b0[j] = su[n * ST + kb];
                b1[j] = su[n * ST + kb + 4];
            }
            #pragma unroll
            for (int mt = 0; mt < 4; mt++) {
                const uint32_t* spr = sp + (mt * 16 + gid) * ST;
                uint32_t a0 = spr[kb];
                uint32_t a1 = spr[8 * ST + kb];
                uint32_t a2 = spr[kb + 4];
                uint32_t a3 = spr[8 * ST + kb + 4];
                #pragma unroll
                for (int j = 0; j < 4; j++)
                    MMA_TF32(acc[mt][j][0], acc[mt][j][1], acc[mt][j][2], acc[mt][j][3],
                             a0, a1, a2, a3, b0[j], b1[j]);
            }
        }

        // epilogue: out = z + delta
        #pragma unroll
        for (int mt = 0; mt < 4; mt++) {
            int row = mt * 16 + gid;
            #pragma unroll
            for (int half = 0; half < 2; half++) {
                int rr = row + half * 8;
                if (rr < nc) {
                    int gs = g_sorted[off + m0 + rr];
                    const float* zrow = z + (size_t)gs * HH + h0;
                    float* orow = out + (size_t)gs * HH + h0;
                    #pragma unroll
                    for (int j = 0; j < 4; j++) {
                        int col = w * 32 + j * 8 + 2 * tig;
                        float2 zz = *(const float2*)&zrow[col];
                        float c0 = acc[mt][j][half * 2 + 0];
                        float c1 = acc[mt][j][half * 2 + 1];
                        *(float2*)&orow[col] = make_float2(zz.x + c0, zz.y + c1);
                    }
                }
            }
        }
    }
}

// ---------------------------------------------------------------------------
extern "C" void kernel_launch(void* const* d_in, const int* in_sizes, int n_in,
                              void* d_out, int out_size) {
    const float* z   = (const float*)d_in[0];
    const int*   ids = (const int*)  d_in[1];
    const float* u   = (const float*)d_in[2];
    const float* v   = (const float*)d_in[3];
    float*       out = (float*)d_out;

    const int proj_smem = (MT * ST + 64 * ST) * 4;         // 36.9 KB
    const int out_smem  = (MT * ST + HT * ST) * 4;         // 55.3 KB
    cudaFuncSetAttribute(proj_kernel, cudaFuncAttributeMaxDynamicSharedMemorySize, proj_smem);
    cudaFuncSetAttribute(out_kernel,  cudaFuncAttributeMaxDynamicSharedMemorySize, out_smem);

    setup_kernel<<<1, 256>>>(ids);
    proj_kernel<<<dim3(NKG, LL), TPB, proj_smem>>>(z, v);
    reduce_kernel<<<(BB * RNK / 4 + 255) / 256, 256>>>();
    out_kernel<<<dim3(HH / HT, LL), TPB, out_smem>>>(z, u, out);
}